// round 1
// baseline (speedup 1.0000x reference)
#include <cuda_runtime.h>
#include <math.h>

#define BATCH 2
#define SEQ   2048
#define NH    16
#define HD    64
#define EMB   1024
#define MTOT  (BATCH*SEQ)
#define PADW  68

// Scratch (allocation-free): Q/K/V in [b][h][s][d] layout, 16 MB each.
static __device__ float g_q[BATCH*NH*SEQ*HD];
static __device__ float g_k[BATCH*NH*SEQ*HD];
static __device__ float g_v[BATCH*NH*SEQ*HD];

// ---------------------------------------------------------------------------
// QKV projection: C[m][n] = sum_k X[m][k] * W[n][k] + bias[n]
// 64x64 block tile, BK=16, 4x4 per thread. grid.z selects Q/K/V.
// Epilogue scatters into [b][h][s][d] scratch.
// ---------------------------------------------------------------------------
__global__ __launch_bounds__(256) void qkv_gemm_kernel(
    const float* __restrict__ X,
    const float* __restrict__ Wq, const float* __restrict__ bq,
    const float* __restrict__ Wk, const float* __restrict__ bk,
    const float* __restrict__ Wv, const float* __restrict__ bv)
{
    const float *W, *bias;
    float *out;
    if (blockIdx.z == 0)      { W = Wq; bias = bq; out = g_q; }
    else if (blockIdx.z == 1) { W = Wk; bias = bk; out = g_k; }
    else                      { W = Wv; bias = bv; out = g_v; }

    __shared__ float Xs[16][64];
    __shared__ float Ws[16][64];

    const int tid = threadIdx.x;
    const int tx = tid & 15, ty = tid >> 4;
    const int m0 = blockIdx.y * 64;
    const int n0 = blockIdx.x * 64;
    const int lrow = tid >> 2;        // 0..63
    const int lk4  = (tid & 3) << 2;  // 0,4,8,12

    const float* xg = X + (size_t)(m0 + lrow) * EMB + lk4;
    const float* wg = W + (size_t)(n0 + lrow) * EMB + lk4;

    float acc[4][4] = {};
    for (int k0 = 0; k0 < EMB; k0 += 16) {
        float4 xv = *(const float4*)(xg + k0);
        float4 wv = *(const float4*)(wg + k0);
        __syncthreads();
        Xs[lk4+0][lrow] = xv.x; Xs[lk4+1][lrow] = xv.y;
        Xs[lk4+2][lrow] = xv.z; Xs[lk4+3][lrow] = xv.w;
        Ws[lk4+0][lrow] = wv.x; Ws[lk4+1][lrow] = wv.y;
        Ws[lk4+2][lrow] = wv.z; Ws[lk4+3][lrow] = wv.w;
        __syncthreads();
        #pragma unroll
        for (int kk = 0; kk < 16; kk++) {
            float4 xr = *(const float4*)&Xs[kk][ty << 2];
            float4 wr = *(const float4*)&Ws[kk][tx << 2];
            float xa[4] = {xr.x, xr.y, xr.z, xr.w};
            float wa[4] = {wr.x, wr.y, wr.z, wr.w};
            #pragma unroll
            for (int i = 0; i < 4; i++)
                #pragma unroll
                for (int j = 0; j < 4; j++)
                    acc[i][j] += xa[i] * wa[j];
        }
    }

    const int b = m0 / SEQ;
    const int h = n0 / HD;
    const int dd0 = (n0 - h*HD) + (tx << 2);   // 0..60, multiple of 4
    float4 bvv = *(const float4*)&bias[n0 + (tx << 2)];
    float ba[4] = {bvv.x, bvv.y, bvv.z, bvv.w};
    #pragma unroll
    for (int i = 0; i < 4; i++) {
        int m = m0 + (ty << 2) + i;
        int s = m - b*SEQ;
        float4 o;
        o.x = acc[i][0] + ba[0];
        o.y = acc[i][1] + ba[1];
        o.z = acc[i][2] + ba[2];
        o.w = acc[i][3] + ba[3];
        *(float4*)&out[(((size_t)(b*NH + h))*SEQ + s)*HD + dd0] = o;
    }
}

// ---------------------------------------------------------------------------
// RoPE in place on g_q and g_k. One thread per (tensor, b, h, s, i<32) pair.
// q'[i]    = q[i]*cos(f_i)    - q[i+32]*sin(f_i)
// q'[i+32] = q[i+32]*cos(f_i) + q[i]*sin(f_i),  f_i = s * 10000^(-i/32)
// ---------------------------------------------------------------------------
__global__ void rope_kernel()
{
    int idx = blockIdx.x * blockDim.x + threadIdx.x;
    const int per = BATCH*NH*SEQ*32;      // 2^21
    if (idx >= 2*per) return;
    float* buf = g_q;
    if (idx >= per) { buf = g_k; idx -= per; }
    const int i  = idx & 31;
    const int s  = (idx >> 5) & (SEQ - 1);
    const int bh = idx >> 16;             // 0..31
    const float inv = expf(-(float)i * (logf(10000.0f) / 32.0f));
    const float f = (float)s * inv;
    float sn, cs;
    sincosf(f, &sn, &cs);
    const size_t base = ((size_t)bh * SEQ + s) * HD;
    const float lo = buf[base + i];
    const float hi = buf[base + i + 32];
    buf[base + i]      = lo*cs - hi*sn;
    buf[base + i + 32] = hi*cs + lo*sn;
}

// ---------------------------------------------------------------------------
// Flash attention: one block per (b, h, 64-row q tile). Br=Bc=64, d=64.
// 16x16 thread grid, 4x4 per thread. Online softmax, shfl row reductions.
// Smem: QT[kk][r], KT[kk][c], VS[kk][c], PT[c][r]  each [64][PADW].
// ---------------------------------------------------------------------------
__global__ __launch_bounds__(256) void flash_kernel(
    const float* __restrict__ mask, float* __restrict__ out)
{
    extern __shared__ float sm[];
    float* QT = sm;                 // QT[kk*PADW + r] = Q[r][kk]
    float* KT = sm + 64*PADW;       // KT[kk*PADW + c] = K[c][kk]
    float* VS = sm + 2*64*PADW;     // VS[kk*PADW + c] = V[kk][c]
    float* PT = sm + 3*64*PADW;     // PT[c*PADW + r]  = P[r][c]

    const int tid = threadIdx.x;
    const int tx = tid & 15, ty = tid >> 4;
    const int q0 = blockIdx.x * 64;
    const int h  = blockIdx.y;
    const int b  = blockIdx.z;

    const size_t hbase = ((size_t)(b*NH + h)) * SEQ * HD;
    const float* qg = g_q + hbase;
    const float* kg = g_k + hbase;
    const float* vg = g_v + hbase;
    const float* mk = mask + (size_t)b * SEQ;

    // Load Q tile transposed (done once)
    #pragma unroll
    for (int i = 0; i < 4; i++) {
        int f = i*256 + tid;
        int row = f >> 4;
        int c4  = (f & 15) << 2;
        float4 v = *(const float4*)(qg + (size_t)(q0 + row)*HD + c4);
        QT[(c4+0)*PADW + row] = v.x;
        QT[(c4+1)*PADW + row] = v.y;
        QT[(c4+2)*PADW + row] = v.z;
        QT[(c4+3)*PADW + row] = v.w;
    }

    float acc[4][4] = {};
    float mprev[4], lsum[4];
    #pragma unroll
    for (int i = 0; i < 4; i++) { mprev[i] = -INFINITY; lsum[i] = 0.f; }

    for (int t = 0; t < SEQ/64; t++) {
        const int k0 = t * 64;

        // Load K (transposed) and V (row-major) tiles
        #pragma unroll
        for (int i = 0; i < 4; i++) {
            int f = i*256 + tid;
            int row = f >> 4;
            int c4  = (f & 15) << 2;
            float4 kv = *(const float4*)(kg + (size_t)(k0 + row)*HD + c4);
            KT[(c4+0)*PADW + row] = kv.x;
            KT[(c4+1)*PADW + row] = kv.y;
            KT[(c4+2)*PADW + row] = kv.z;
            KT[(c4+3)*PADW + row] = kv.w;
            float4 vv = *(const float4*)(vg + (size_t)(k0 + row)*HD + c4);
            *(float4*)&VS[row*PADW + c4] = vv;
        }
        __syncthreads();

        // S = Q K^T  (4x4 per thread)
        float sv[4][4] = {};
        #pragma unroll 4
        for (int kk = 0; kk < 64; kk++) {
            float4 qv = *(const float4*)&QT[kk*PADW + (ty << 2)];
            float4 kv = *(const float4*)&KT[kk*PADW + (tx << 2)];
            float qa[4] = {qv.x, qv.y, qv.z, qv.w};
            float ka[4] = {kv.x, kv.y, kv.z, kv.w};
            #pragma unroll
            for (int i = 0; i < 4; i++)
                #pragma unroll
                for (int j = 0; j < 4; j++)
                    sv[i][j] += qa[i] * ka[j];
        }

        // scale + mask
        float mv[4];
        #pragma unroll
        for (int j = 0; j < 4; j++) mv[j] = mk[k0 + (tx << 2) + j];
        #pragma unroll
        for (int i = 0; i < 4; i++)
            #pragma unroll
            for (int j = 0; j < 4; j++)
                sv[i][j] = sv[i][j] * 0.125f + mv[j];

        // online softmax
        #pragma unroll
        for (int i = 0; i < 4; i++) {
            float rm = fmaxf(fmaxf(sv[i][0], sv[i][1]), fmaxf(sv[i][2], sv[i][3]));
            #pragma unroll
            for (int d = 8; d >= 1; d >>= 1)
                rm = fmaxf(rm, __shfl_xor_sync(0xffffffffu, rm, d));
            float mnew = fmaxf(mprev[i], rm);
            float corr = __expf(mprev[i] - mnew);   // exp(-inf) = 0 on first tile
            float rs = 0.f;
            #pragma unroll
            for (int j = 0; j < 4; j++) {
                float p = __expf(sv[i][j] - mnew);
                PT[((tx << 2) + j)*PADW + (ty << 2) + i] = p;
                rs += p;
            }
            #pragma unroll
            for (int d = 8; d >= 1; d >>= 1)
                rs += __shfl_xor_sync(0xffffffffu, rs, d);
            lsum[i] = lsum[i]*corr + rs;
            #pragma unroll
            for (int j = 0; j < 4; j++) acc[i][j] *= corr;
            mprev[i] = mnew;
        }
        __syncthreads();

        // O += P V
        #pragma unroll 4
        for (int kk = 0; kk < 64; kk++) {
            float4 pv = *(const float4*)&PT[kk*PADW + (ty << 2)];
            float4 vv = *(const float4*)&VS[kk*PADW + (tx << 2)];
            float pa[4] = {pv.x, pv.y, pv.z, pv.w};
            float va[4] = {vv.x, vv.y, vv.z, vv.w};
            #pragma unroll
            for (int i = 0; i < 4; i++)
                #pragma unroll
                for (int j = 0; j < 4; j++)
                    acc[i][j] += pa[i] * va[j];
        }
        __syncthreads();
    }

    // Normalize + write out[b][s][h*64+d]
    #pragma unroll
    for (int i = 0; i < 4; i++) {
        float invl = 1.0f / lsum[i];
        int s = q0 + (ty << 2) + i;
        float4 o;
        o.x = acc[i][0]*invl;
        o.y = acc[i][1]*invl;
        o.z = acc[i][2]*invl;
        o.w = acc[i][3]*invl;
        *(float4*)&out[((size_t)(b*SEQ + s))*EMB + h*HD + (tx << 2)] = o;
    }
}

// ---------------------------------------------------------------------------
extern "C" void kernel_launch(void* const* d_in, const int* in_sizes, int n_in,
                              void* d_out, int out_size)
{
    const float* x    = (const float*)d_in[0];
    const float* mask = (const float*)d_in[1];
    const float* Wq   = (const float*)d_in[2];
    const float* bq   = (const float*)d_in[3];
    const float* Wk   = (const float*)d_in[4];
    const float* bk   = (const float*)d_in[5];
    const float* Wv   = (const float*)d_in[6];
    const float* bv   = (const float*)d_in[7];
    float* out = (float*)d_out;

    dim3 ggrid(EMB/64, MTOT/64, 3);
    qkv_gemm_kernel<<<ggrid, 256>>>(x, Wq, bq, Wk, bk, Wv, bv);

    const int rtot = 2*BATCH*NH*SEQ*32;
    rope_kernel<<<(rtot + 255)/256, 256>>>();

    const int flash_smem = 4*64*PADW*(int)sizeof(float);  // 69632 B
    cudaFuncSetAttribute(flash_kernel,
                         cudaFuncAttributeMaxDynamicSharedMemorySize, flash_smem);
    dim3 fgrid(SEQ/64, NH, BATCH);
    flash_kernel<<<fgrid, 256, flash_smem>>>(mask, out);
}